// round 12
// baseline (speedup 1.0000x reference)
#include <cuda_runtime.h>
#include <math.h>
#include <stdint.h>

// ---------------- problem constants ----------------
#define BB      64
#define NP      377
#define NROWS   (BB * NP)        // 24128 = 377 * 64
#define CIN     384
#define HID     128
#define H2X     256
#define SD      16
#define KNEI    6
#define PIN_DIM (SD * (KNEI + 1)) // 112
#define NSTEPS  16
#define FH      37
#define DHH     518
#define CCHUNK  8                // channels per sample_feat block

// fused_step dynamic smem layout (floats)
#define FS_AS_OFF   0                       // As[2][16][68]  = 2176
#define FS_WS_OFF   2176                    // Ws[2][16][128] = 4096
#define FS_HS_OFF   (2176 + 4096)           // Hs[128][68]    = 8704 (also reduce buf)
#define FS_B1_OFF   (FS_HS_OFF + 8704)      // bp2s[128]
#define FS_B2_OFF   (FS_B1_OFF + 128)       // bu1s[128]
#define FS_B3_OFF   (FS_B2_OFF + 128)       // bu2s[16]
#define FS_TOTAL_F  (FS_B3_OFF + 16)        // 15248 floats
#define FS_TOTAL_B  (FS_TOTAL_F * 4)        // 60992 bytes

typedef unsigned long long u64;

// ---- packed f32x2 helpers (sm_100a) -----------------------------------------
__device__ __forceinline__ u64 bcast2(float x) {
    u64 r;
    asm("mov.b64 %0, {%1, %1};" : "=l"(r) : "f"(x));
    return r;
}
__device__ __forceinline__ void fma2(u64& acc, u64 a, u64 w) {
    asm("fma.rn.f32x2 %0, %1, %2, %0;" : "+l"(acc) : "l"(a), "l"(w));
}
__device__ __forceinline__ void unpack2(u64 v, float& lo, float& hi) {
    asm("mov.b64 {%0, %1}, %2;" : "=f"(lo), "=f"(hi) : "l"(v));
}

// ---- cp.async helpers --------------------------------------------------------
__device__ __forceinline__ void cp16(void* dst_smem, const void* src_gmem) {
    uint32_t d = (uint32_t)__cvta_generic_to_shared(dst_smem);
    asm volatile("cp.async.cg.shared.global [%0], [%1], 16;" :: "r"(d), "l"(src_gmem));
}
__device__ __forceinline__ void cp_commit() {
    asm volatile("cp.async.commit_group;");
}
__device__ __forceinline__ void cp_wait0() {
    asm volatile("cp.async.wait_group 0;" ::: "memory");
}

// ---------------- scratch ----------------------------------------------------
__device__ float g_Fs[(size_t)NROWS * CIN];
__device__ float g_dep[NROWS];
__device__ float g_bufA[(size_t)NROWS * H2X];
__device__ float g_bufB[(size_t)NROWS * HID];
__device__ float g_init[(size_t)NROWS * SD];
__device__ float g_state[(size_t)NROWS * SD];
__device__ float g_pin[(size_t)NROWS * PIN_DIM];

// ---------------- feature bilinear sampling (smem-image, coalesced) ----------
__global__ void __launch_bounds__(256) sample_feat_kernel(
        const float* __restrict__ feat,
        const float* __restrict__ sx,
        const float* __restrict__ sy) {
    __shared__ float img[CCHUNK * FH * FH];   // 8 * 1369 floats = 43808 B

    int b  = blockIdx.x;
    int c0 = blockIdx.y * CCHUNK;

    const float* src = feat + ((size_t)b * CIN + c0) * FH * FH;
    for (int i = threadIdx.x; i < CCHUNK * FH * FH; i += 256) img[i] = src[i];
    __syncthreads();

    for (int it = threadIdx.x; it < NP * CCHUNK; it += 256) {
        int n = it >> 3, cc = it & 7;
        float gx = sx[n], gy = sy[n];
        float ix = fminf(fmaxf((gx + 1.0f) * 0.5f * (float)(FH - 1), 0.0f), (float)(FH - 1));
        float iy = fminf(fmaxf((gy + 1.0f) * 0.5f * (float)(FH - 1), 0.0f), (float)(FH - 1));
        int x0 = (int)floorf(ix), y0 = (int)floorf(iy);
        int x1 = min(x0 + 1, FH - 1), y1 = min(y0 + 1, FH - 1);
        float wx = ix - (float)x0, wy = iy - (float)y0;
        float w00 = (1.0f - wx) * (1.0f - wy);
        float w01 = wx * (1.0f - wy);
        float w10 = (1.0f - wx) * wy;
        float w11 = wx * wy;

        const float* p = img + cc * FH * FH;
        float v = p[y0 * FH + x0] * w00 + p[y0 * FH + x1] * w01 +
                  p[y1 * FH + x0] * w10 + p[y1 * FH + x1] * w11;
        g_Fs[((size_t)b * NP + n) * CIN + c0 + cc] = v;
    }
}

// ---------------- depth bilinear sampling ------------------------------------
__global__ void sample_depth_kernel(const float* __restrict__ depth,
                                    const float* __restrict__ sx,
                                    const float* __restrict__ sy) {
    int row = blockIdx.x * blockDim.x + threadIdx.x;
    if (row >= NROWS) return;
    int b = row / NP, n = row % NP;
    float gx = sx[n], gy = sy[n];
    float jx = fminf(fmaxf((gx + 1.0f) * 0.5f * (float)(DHH - 1), 0.0f), (float)(DHH - 1));
    float jy = fminf(fmaxf((gy + 1.0f) * 0.5f * (float)(DHH - 1), 0.0f), (float)(DHH - 1));
    int a0 = (int)floorf(jx), c0 = (int)floorf(jy);
    int a1 = min(a0 + 1, DHH - 1), c1 = min(c0 + 1, DHH - 1);
    float ux = jx - (float)a0, uy = jy - (float)c0;
    const float* dp = depth + (size_t)b * DHH * DHH;
    float v = dp[c0 * DHH + a0] * (1.0f - ux) * (1.0f - uy) +
              dp[c0 * DHH + a1] * ux * (1.0f - uy) +
              dp[c1 * DHH + a0] * (1.0f - ux) * uy +
              dp[c1 * DHH + a1] * ux * uy;
    g_dep[row] = v;
}

// ---- 8-deep k micro-kernel, 8x8 tile, packed --------------------------------
__device__ __forceinline__ void mma_tile8(
    u64 acc64[8][4], const float (*As8)[68], const float (*Ws8)[128],
    int r8, int c16) {
#pragma unroll
    for (int kk = 0; kk < 8; kk++) {
        float4 a0 = *reinterpret_cast<const float4*>(&As8[kk][r8 * 4]);
        float4 a1 = *reinterpret_cast<const float4*>(&As8[kk][32 + r8 * 4]);
        ulonglong2 wva = *reinterpret_cast<const ulonglong2*>(&Ws8[kk][c16 * 8]);
        ulonglong2 wvb = *reinterpret_cast<const ulonglong2*>(&Ws8[kk][c16 * 8 + 4]);
        u64 wpk[4] = {wva.x, wva.y, wvb.x, wvb.y};
        u64 ab[8] = {bcast2(a0.x), bcast2(a0.y), bcast2(a0.z), bcast2(a0.w),
                     bcast2(a1.x), bcast2(a1.y), bcast2(a1.z), bcast2(a1.w)};
#pragma unroll
        for (int i = 0; i < 8; i++)
#pragma unroll
            for (int j = 0; j < 4; j++) fma2(acc64[i][j], ab[i], wpk[j]);
    }
}

// ---- group-1 -> group-0 reduction of acc rows [r*4, r*4+4) via red buffer ---
__device__ __forceinline__ void red_store(float* red, u64 acc64[8][4], int r, int wt) {
#pragma unroll
    for (int i = 0; i < 4; i++)
#pragma unroll
        for (int j = 0; j < 4; j++) {
            float lo, hi;
            unpack2(acc64[r * 4 + i][j], lo, hi);
            red[(i * 8 + 2 * j) * 128 + wt] = lo;
            red[(i * 8 + 2 * j + 1) * 128 + wt] = hi;
        }
}
__device__ __forceinline__ void red_add(const float* red, float accf[8][8], int r, int wt) {
#pragma unroll
    for (int i = 0; i < 4; i++)
#pragma unroll
        for (int j2 = 0; j2 < 8; j2++)
            accf[r * 4 + i][j2] += red[(i * 8 + j2) * 128 + wt];
}

// ---------------- 64x128 GEMM, 256 thr, K-split groups, cp.async W staging ---
// launch_bounds (256,3): cap regs at ~85 so 3 blocks/SM fit the register file.
template <int EPI>
__global__ void __launch_bounds__(256, 3)
gemm64x128(const float* __restrict__ A, const float* __restrict__ W,
           const float* __restrict__ bias, float* __restrict__ C,
           int K, int N) {
    __shared__ __align__(16) float As[2][16][68];
    __shared__ __align__(16) float Ws[2][16][128];

    int m0 = blockIdx.x * 64;
    int n0 = blockIdx.y * 128;
    int tid = threadIdx.x;
    int g   = tid >> 7;
    int wt  = tid & 127;
    int r8 = wt & 7, c16 = wt >> 3;

    int am = tid >> 2;
    int aq = (tid & 3) * 4;
    int wk = tid >> 5;             // 0..7
    int wn = (tid & 31) * 4;

    u64 acc64[8][4];
#pragma unroll
    for (int i = 0; i < 8; i++)
#pragma unroll
        for (int j = 0; j < 4; j++) acc64[i][j] = 0ull;

    // preload tile 0: A via regs, W via cp.async
    {
        float4 v = *reinterpret_cast<const float4*>(&A[(size_t)(m0 + am) * K + aq]);
        As[0][aq + 0][am] = v.x;
        As[0][aq + 1][am] = v.y;
        As[0][aq + 2][am] = v.z;
        As[0][aq + 3][am] = v.w;
#pragma unroll
        for (int i = 0; i < 2; i++) {
            int k = wk + i * 8;
            cp16(&Ws[0][k][wn], &W[(size_t)k * N + n0 + wn]);
        }
        cp_commit();
    }
    cp_wait0();
    __syncthreads();

    int KT = K >> 4;
    int p = 0;
    for (int t = 0; t < KT; t++) {
        float4 pa;
        bool has = (t + 1 < KT);
        int q = p ^ 1;
        if (has) {
            int k0 = (t + 1) << 4;
#pragma unroll
            for (int i = 0; i < 2; i++) {
                int k = wk + i * 8;
                cp16(&Ws[q][k][wn], &W[(size_t)(k0 + k) * N + n0 + wn]);
            }
            cp_commit();
            pa = *reinterpret_cast<const float4*>(&A[(size_t)(m0 + am) * K + k0 + aq]);
        }

        mma_tile8(acc64,
                  reinterpret_cast<const float (*)[68]>(&As[p][g * 8][0]),
                  reinterpret_cast<const float (*)[128]>(&Ws[p][g * 8][0]),
                  r8, c16);

        if (has) {
            As[q][aq + 0][am] = pa.x;
            As[q][aq + 1][am] = pa.y;
            As[q][aq + 2][am] = pa.z;
            As[q][aq + 3][am] = pa.w;
            cp_wait0();
        }
        __syncthreads();
        p ^= 1;
    }

    // ---- cross-group reduction (red buffer aliases Ws: 4096 floats) ----
    float* red = &Ws[0][0][0];
    float accf[8][8];
    if (g == 0) {
#pragma unroll
        for (int i = 0; i < 8; i++)
#pragma unroll
            for (int j = 0; j < 4; j++) unpack2(acc64[i][j], accf[i][2 * j], accf[i][2 * j + 1]);
    }
#pragma unroll
    for (int r = 0; r < 2; r++) {
        if (g == 1) red_store(red, acc64, r, wt);
        __syncthreads();
        if (g == 0) red_add(red, accf, r, wt);
        __syncthreads();
    }

    if (g == 0) {
        float bb[8];
#pragma unroll
        for (int j = 0; j < 8; j++) bb[j] = bias[n0 + c16 * 8 + j];
#pragma unroll
        for (int h = 0; h < 2; h++) {
#pragma unroll
            for (int i = 0; i < 4; i++) {
                int m = m0 + h * 32 + r8 * 4 + i;
                int ai = h * 4 + i;
                float v[8];
#pragma unroll
                for (int j = 0; j < 8; j++) {
                    v[j] = accf[ai][j] + bb[j];
                    if (EPI == 0) v[j] = fmaxf(v[j], 0.0f);
                }
                float4* cp = reinterpret_cast<float4*>(&C[(size_t)m * N + n0 + c16 * 8]);
                cp[0] = make_float4(v[0], v[1], v[2], v[3]);
                cp[1] = make_float4(v[4], v[5], v[6], v[7]);
            }
        }
    }
}

// ---------------- small GEMM (N=16), used once for wi3 -----------------------
template <int BM, int BN, int BK, int TM, int TN, int EPI>
__global__ void gemm_kernel(const float* __restrict__ A,
                            const float* __restrict__ W,
                            const float* __restrict__ bias,
                            float* __restrict__ C,
                            int K, int N) {
    constexpr int TX = BN / TN;
    constexpr int TY = BM / TM;
    static_assert(TX * TY == 256, "256 threads");
    constexpr int AS = BM + 4;
    __shared__ float As[BK][AS];
    __shared__ float Ws[BK][BN];

    int m0 = blockIdx.x * BM;
    int n0 = blockIdx.y * BN;
    int tid = threadIdx.x;
    int tx = tid % TX, ty = tid / TX;

    float acc[TM][TN];
#pragma unroll
    for (int i = 0; i < TM; i++)
#pragma unroll
        for (int j = 0; j < TN; j++) acc[i][j] = 0.0f;

    int am = tid >> 2;
    int aq = (tid & 3) * 4;

    for (int k0 = 0; k0 < K; k0 += BK) {
        {
            const float4 v = *reinterpret_cast<const float4*>(
                &A[(size_t)(m0 + am) * K + k0 + aq]);
            As[aq + 0][am] = v.x;
            As[aq + 1][am] = v.y;
            As[aq + 2][am] = v.z;
            As[aq + 3][am] = v.w;
        }
        for (int i = tid; i < BK * BN; i += 256) {
            int k = i / BN, n = i % BN;
            Ws[k][n] = W[(size_t)(k0 + k) * N + n0 + n];
        }
        __syncthreads();
#pragma unroll
        for (int kk = 0; kk < BK; kk++) {
            float a[TM], w[TN];
#pragma unroll
            for (int i = 0; i < TM; i++) a[i] = As[kk][ty * TM + i];
#pragma unroll
            for (int j = 0; j < TN; j++) w[j] = Ws[kk][tx * TN + j];
#pragma unroll
            for (int i = 0; i < TM; i++)
#pragma unroll
                for (int j = 0; j < TN; j++) acc[i][j] += a[i] * w[j];
        }
        __syncthreads();
    }
#pragma unroll
    for (int i = 0; i < TM; i++) {
        int m = m0 + ty * TM + i;
#pragma unroll
        for (int j = 0; j < TN; j++) {
            int n = n0 + tx * TN + j;
            float v = acc[i][j] + bias[n];
            if (EPI == 0) v = fmaxf(v, 0.0f);
            C[(size_t)m * N + n] = v;
        }
    }
}

// ---------------- fused wp2 -> wu1 -> wu2 -> state update --------------------
__global__ void __launch_bounds__(256, 3)
fused_step(const float* __restrict__ A,           // g_bufA (h1), row len 256
           const float* __restrict__ wp2, const float* __restrict__ bp2,
           const float* __restrict__ wu1, const float* __restrict__ bu1,
           const float* __restrict__ wu2, const float* __restrict__ bu2,
           const float* __restrict__ sstep,
           float* __restrict__ state) {
    extern __shared__ __align__(16) float dyn[];
    float (*As)[16][68]  = reinterpret_cast<float (*)[16][68]>(dyn + FS_AS_OFF);
    float (*Ws)[16][128] = reinterpret_cast<float (*)[16][128]>(dyn + FS_WS_OFF);
    float (*Hs)[68]      = reinterpret_cast<float (*)[68]>(dyn + FS_HS_OFF);
    float* redH = dyn + FS_HS_OFF;
    float* bp2s = dyn + FS_B1_OFF;
    float* bu1s = dyn + FS_B2_OFF;
    float* bu2s = dyn + FS_B3_OFF;

    int m0 = blockIdx.x * 64;
    int tid = threadIdx.x;
    int g   = tid >> 7;
    int wt  = tid & 127;
    int r8 = wt & 7, c16 = wt >> 3;
    int am = tid >> 2;
    int aq = (tid & 3) * 4;
    int wk = tid >> 5;
    int wn = (tid & 31) * 4;

    if (tid < 128) { bp2s[tid] = bp2[tid]; bu1s[tid] = bu1[tid]; }
    if (tid < 16)  { bu2s[tid] = bu2[tid]; }

    u64 acc64[8][4];
#pragma unroll
    for (int i = 0; i < 8; i++)
#pragma unroll
        for (int j = 0; j < 4; j++) acc64[i][j] = 0ull;

    // ---- phase 1: h2 = relu(h1 @ wp2 + bp2), K=256 ----
    {
        float4 v = *reinterpret_cast<const float4*>(&A[(size_t)(m0 + am) * 256 + aq]);
        As[0][aq + 0][am] = v.x;
        As[0][aq + 1][am] = v.y;
        As[0][aq + 2][am] = v.z;
        As[0][aq + 3][am] = v.w;
#pragma unroll
        for (int i = 0; i < 2; i++) {
            int k = wk + i * 8;
            cp16(&Ws[0][k][wn], &wp2[(size_t)k * 128 + wn]);
        }
        cp_commit();
    }
    cp_wait0();
    __syncthreads();

    int p = 0;
    for (int t = 0; t < 16; t++) {
        float4 pa;
        bool has = (t + 1 < 16);
        int q = p ^ 1;
        if (has) {
            int k0 = (t + 1) << 4;
#pragma unroll
            for (int i = 0; i < 2; i++) {
                int k = wk + i * 8;
                cp16(&Ws[q][k][wn], &wp2[(size_t)(k0 + k) * 128 + wn]);
            }
            cp_commit();
            pa = *reinterpret_cast<const float4*>(&A[(size_t)(m0 + am) * 256 + k0 + aq]);
        }
        mma_tile8(acc64,
                  reinterpret_cast<const float (*)[68]>(&As[p][g * 8][0]),
                  reinterpret_cast<const float (*)[128]>(&Ws[p][g * 8][0]),
                  r8, c16);
        if (has) {
            As[q][aq + 0][am] = pa.x;
            As[q][aq + 1][am] = pa.y;
            As[q][aq + 2][am] = pa.z;
            As[q][aq + 3][am] = pa.w;
            cp_wait0();
        }
        __syncthreads();
        p ^= 1;
    }

    // reduction (redH = Hs area) + h2 store + wu1 tile-0 async stage
    {
        float accf[8][8];
        if (g == 0) {
#pragma unroll
            for (int i = 0; i < 8; i++)
#pragma unroll
                for (int j = 0; j < 4; j++) unpack2(acc64[i][j], accf[i][2 * j], accf[i][2 * j + 1]);
        }
#pragma unroll
        for (int r = 0; r < 2; r++) {
            if (g == 1) red_store(redH, acc64, r, wt);
            __syncthreads();
            if (g == 0) red_add(redH, accf, r, wt);
            __syncthreads();
        }
        if (g == 0) {
#pragma unroll
            for (int j = 0; j < 8; j++) {
                int n = c16 * 8 + j;
                float v0[4], v1[4];
#pragma unroll
                for (int i = 0; i < 4; i++) v0[i] = fmaxf(accf[i][j] + bp2s[n], 0.0f);
#pragma unroll
                for (int i = 0; i < 4; i++) v1[i] = fmaxf(accf[4 + i][j] + bp2s[n], 0.0f);
                *reinterpret_cast<float4*>(&Hs[n][r8 * 4])      = make_float4(v0[0], v0[1], v0[2], v0[3]);
                *reinterpret_cast<float4*>(&Hs[n][32 + r8 * 4]) = make_float4(v1[0], v1[1], v1[2], v1[3]);
            }
        }
#pragma unroll
        for (int i = 0; i < 2; i++) {
            int k = wk + i * 8;
            cp16(&Ws[0][k][wn], &wu1[(size_t)k * 128 + wn]);
        }
        cp_commit();
        cp_wait0();
        __syncthreads();
    }

    // ---- phase 2: dh = relu(h2 @ wu1 + bu1), K=128, A in Hs ----
#pragma unroll
    for (int i = 0; i < 8; i++)
#pragma unroll
        for (int j = 0; j < 4; j++) acc64[i][j] = 0ull;

    p = 0;
    for (int c = 0; c < 8; c++) {
        bool has = (c + 1 < 8);
        int q = p ^ 1;
        if (has) {
            int k0 = (c + 1) << 4;
#pragma unroll
            for (int i = 0; i < 2; i++) {
                int k = wk + i * 8;
                cp16(&Ws[q][k][wn], &wu1[(size_t)(k0 + k) * 128 + wn]);
            }
            cp_commit();
        }
        mma_tile8(acc64,
                  reinterpret_cast<const float (*)[68]>(&Hs[c * 16 + g * 8][0]),
                  reinterpret_cast<const float (*)[128]>(&Ws[p][g * 8][0]),
                  r8, c16);
        if (has) cp_wait0();
        __syncthreads();
        p ^= 1;
    }

    // reduction (redH) + dh store + wu2 staging
    {
        float accf[8][8];
        if (g == 0) {
#pragma unroll
            for (int i = 0; i < 8; i++)
#pragma unroll
                for (int j = 0; j < 4; j++) unpack2(acc64[i][j], accf[i][2 * j], accf[i][2 * j + 1]);
        }
#pragma unroll
        for (int r = 0; r < 2; r++) {
            if (g == 1) red_store(redH, acc64, r, wt);
            __syncthreads();
            if (g == 0) red_add(redH, accf, r, wt);
            __syncthreads();
        }
        if (g == 0) {
#pragma unroll
            for (int j = 0; j < 8; j++) {
                int n = c16 * 8 + j;
                float v0[4], v1[4];
#pragma unroll
                for (int i = 0; i < 4; i++) v0[i] = fmaxf(accf[i][j] + bu1s[n], 0.0f);
#pragma unroll
                for (int i = 0; i < 4; i++) v1[i] = fmaxf(accf[4 + i][j] + bu1s[n], 0.0f);
                *reinterpret_cast<float4*>(&Hs[n][r8 * 4])      = make_float4(v0[0], v0[1], v0[2], v0[3]);
                *reinterpret_cast<float4*>(&Hs[n][32 + r8 * 4]) = make_float4(v1[0], v1[1], v1[2], v1[3]);
            }
        }
        {
            float* wflat = &Ws[0][0][0];
#pragma unroll
            for (int i = 0; i < 2; i++) {
                int f = (tid + i * 256) * 4;   // 2048 floats
                cp16(&wflat[f], &wu2[f]);
            }
            cp_commit();
            cp_wait0();
        }
        __syncthreads();
    }

    // ---- phase 3: delta = dh @ wu2 + bu2; state += step*delta ----
    {
        const float* wflat = &Ws[0][0][0];
        int col = tid & 15;
        int rg  = tid >> 4;   // 0..15 -> rows rg*4..+3
        float acc3[4];
#pragma unroll
        for (int i = 0; i < 4; i++) acc3[i] = 0.0f;
#pragma unroll 8
        for (int kk = 0; kk < 128; kk++) {
            float w = wflat[kk * 16 + col];
            float4 a4 = *reinterpret_cast<const float4*>(&Hs[kk][rg * 4]);
            acc3[0] += a4.x * w; acc3[1] += a4.y * w;
            acc3[2] += a4.z * w; acc3[3] += a4.w * w;
        }
        float stp = sstep[0];
        float bv = bu2s[col];
#pragma unroll
        for (int i = 0; i < 4; i++) {
            int m = m0 + rg * 4 + i;
            state[(size_t)m * SD + col] += stp * (acc3[i] + bv);
        }
    }
}

// ---------------- initial state build ----------------------------------------
__global__ void init_state_kernel(const float* __restrict__ sx,
                                  const float* __restrict__ sy,
                                  const float* __restrict__ doff) {
    int row = blockIdx.x * blockDim.x + threadIdx.x;
    if (row >= NROWS) return;
    int n = row % NP;
    const float* ini = g_init + (size_t)row * SD;
    float* st = g_state + (size_t)row * SD;
    st[0] = sx[n] + ini[0] * 0.15f;
    st[1] = sy[n] + ini[1] * 0.15f;
    st[2] = doff[0] + g_dep[row] * -2.0f;
#pragma unroll
    for (int i = 3; i < SD; i++) st[i] = ini[i];
}

// ---------------- fused kNN + pin gather (2 blocks per batch) ----------------
__global__ void __launch_bounds__(384) neighpin_kernel() {
    __shared__ float st[NP * SD];   // 24128 B
    int b = blockIdx.x >> 1;
    int half = blockIdx.x & 1;
    int t = threadIdx.x;

    const float4* gs = reinterpret_cast<const float4*>(g_state + (size_t)b * NP * SD);
    float4* s4 = reinterpret_cast<float4*>(st);
    for (int i = t; i < NP * SD / 4; i += 384) s4[i] = gs[i];
    __syncthreads();

    int pt = half * 189 + t;
    if (t >= 189 || pt >= NP) return;

    float bd[KNEI + 1];
    int bi[KNEI + 1];
#pragma unroll
    for (int i = 0; i <= KNEI; i++) { bd[i] = 3.4e38f; bi[i] = -1; }

    float x = st[pt * SD + 0], y = st[pt * SD + 1], z = st[pt * SD + 2];
    for (int j = 0; j < NP; j++) {
        float dx = x - st[j * SD + 0];
        float dy = y - st[j * SD + 1];
        float dz = z - st[j * SD + 2];
        float d2 = dx * dx + dy * dy + dz * dz;
        if (d2 < bd[KNEI]) {
            int p = KNEI;
            while (p > 0 && bd[p - 1] > d2) {
                bd[p] = bd[p - 1];
                bi[p] = bi[p - 1];
                p--;
            }
            bd[p] = d2;
            bi[p] = j;
        }
    }

    float4* p4 = reinterpret_cast<float4*>(g_pin + (size_t)(b * NP + pt) * PIN_DIM);
    const float4* self = reinterpret_cast<const float4*>(&st[pt * SD]);
#pragma unroll
    for (int q = 0; q < 4; q++) p4[q] = self[q];
#pragma unroll
    for (int k = 0; k < KNEI; k++) {
        const float4* nb = reinterpret_cast<const float4*>(&st[bi[k + 1] * SD]);
#pragma unroll
        for (int q = 0; q < 4; q++) p4[4 + k * 4 + q] = nb[q];
    }
}

// ---------------- postprocess ------------------------------------------------
__device__ __forceinline__ float sgnf(float x) {
    return (x > 0.0f) ? 1.0f : ((x < 0.0f) ? -1.0f : 0.0f);
}

__global__ void final_kernel(float* __restrict__ out) {
    int row = blockIdx.x * blockDim.x + threadIdx.x;
    if (row >= NROWS) return;
    const float* s = g_state + (size_t)row * SD;
    float o[14];
    o[0] = s[0]; o[1] = s[1]; o[2] = s[2];

#pragma unroll
    for (int i = 0; i < 3; i++) {
        float tv = fminf(fmaxf(s[3 + i], -10.0f), 20.0f) + 1.0f;
        float sp = log1pf(expf(tv));
        o[3 + i] = fminf(fmaxf(sp * 0.15f, 1e-6f), 2.0f);
    }

    const float eps = 1e-8f;
    float a1x = s[6], a1y = s[7], a1z = s[8];
    float a2x = s[9], a2y = s[10], a2z = s[11];
    float n1 = sqrtf(a1x * a1x + a1y * a1y + a1z * a1z) + eps;
    float b1x = a1x / n1, b1y = a1y / n1, b1z = a1z / n1;
    float dd = b1x * a2x + b1y * a2y + b1z * a2z;
    float pxv = a2x - dd * b1x, pyv = a2y - dd * b1y, pzv = a2z - dd * b1z;
    float n2 = sqrtf(pxv * pxv + pyv * pyv + pzv * pzv) + eps;
    float b2x = pxv / n2, b2y = pyv / n2, b2z = pzv / n2;
    float b3x = b1y * b2z - b1z * b2y;
    float b3y = b1z * b2x - b1x * b2z;
    float b3z = b1x * b2y - b1y * b2x;
    float m00 = b1x, m11 = b2y, m22 = b3z;
    float qw = 0.5f * sqrtf(fmaxf(1.0f + m00 + m11 + m22, 0.0f) + eps);
    float qx = 0.5f * sqrtf(fmaxf(1.0f + m00 - m11 - m22, 0.0f) + eps) * sgnf(b2z - b3y);
    float qy = 0.5f * sqrtf(fmaxf(1.0f - m00 + m11 - m22, 0.0f) + eps) * sgnf(b3x - b1z);
    float qz = 0.5f * sqrtf(fmaxf(1.0f - m00 - m11 + m22, 0.0f) + eps) * sgnf(b1y - b2x);
    float qn = sqrtf(qw * qw + qx * qx + qy * qy + qz * qz) + eps;
    o[6] = qw / qn; o[7] = qx / qn; o[8] = qy / qn; o[9] = qz / qn;

    o[10] = 1.0f / (1.0f + expf(-s[12]));
    o[11] = 1.0f / (1.0f + expf(-s[13]));
    o[12] = 1.0f / (1.0f + expf(-s[14]));
    o[13] = 1.0f / (1.0f + expf(-s[15]));

    float* op = out + (size_t)row * 14;
#pragma unroll
    for (int i = 0; i < 14; i++) op[i] = o[i];
}

// ---------------- launch ------------------------------------------------------
extern "C" void kernel_launch(void* const* d_in, const int* in_sizes, int n_in,
                              void* d_out, int out_size) {
    const float* feat  = (const float*)d_in[0];
    const float* depth = (const float*)d_in[1];
    const float* sx    = (const float*)d_in[2];
    const float* sy    = (const float*)d_in[3];
    const float* doff  = (const float*)d_in[4];
    const float* sstep = (const float*)d_in[5];
    const float* wi1 = (const float*)d_in[6];
    const float* bi1 = (const float*)d_in[7];
    const float* wi2 = (const float*)d_in[8];
    const float* bi2 = (const float*)d_in[9];
    const float* wi3 = (const float*)d_in[10];
    const float* bi3 = (const float*)d_in[11];
    const float* wp1 = (const float*)d_in[12];
    const float* bp1 = (const float*)d_in[13];
    const float* wp2 = (const float*)d_in[14];
    const float* bp2 = (const float*)d_in[15];
    const float* wu1 = (const float*)d_in[16];
    const float* bu1 = (const float*)d_in[17];
    const float* wu2 = (const float*)d_in[18];
    const float* bu2 = (const float*)d_in[19];

    cudaFuncSetAttribute(fused_step, cudaFuncAttributeMaxDynamicSharedMemorySize,
                         FS_TOTAL_B);

    void *pFs, *pA, *pB, *pInit, *pState, *pPin;
    cudaGetSymbolAddress(&pFs, g_Fs);
    cudaGetSymbolAddress(&pA, g_bufA);
    cudaGetSymbolAddress(&pB, g_bufB);
    cudaGetSymbolAddress(&pInit, g_init);
    cudaGetSymbolAddress(&pState, g_state);
    cudaGetSymbolAddress(&pPin, g_pin);
    float* Fs = (float*)pFs;
    float* bufA = (float*)pA;
    float* bufB = (float*)pB;
    float* initb = (float*)pInit;
    float* state = (float*)pState;
    float* pin = (float*)pPin;

    const int MB = NROWS / 64;  // 377

    // launches 0,1: sampling (launch #3 = gemm64x128 wi2 for ncu)
    sample_feat_kernel<<<dim3(BB, CIN / CCHUNK), 256>>>(feat, sx, sy);
    sample_depth_kernel<<<(NROWS + 127) / 128, 128>>>(depth, sx, sy);

    // launch 2: wi1 (K=384, N=256); launch 3: wi2 (K=256, N=128) <- profiled
    gemm64x128<0><<<dim3(MB, 2), 256>>>(Fs, wi1, bi1, bufA, CIN, H2X);
    gemm64x128<0><<<dim3(MB, 1), 256>>>(bufA, wi2, bi2, bufB, H2X, HID);
    gemm_kernel<64, 16, 16, 4, 1, 1><<<dim3(MB, 1), 256>>>(bufB, wi3, bi3, initb, HID, SD);

    init_state_kernel<<<(NROWS + 255) / 256, 256>>>(sx, sy, doff);

    for (int s = 0; s < NSTEPS; s++) {
        neighpin_kernel<<<BB * 2, 384>>>();
        gemm64x128<0><<<dim3(MB, 2), 256>>>(pin, wp1, bp1, bufA, PIN_DIM, H2X);
        fused_step<<<MB, 256, FS_TOTAL_B>>>(bufA, wp2, bp2, wu1, bu1, wu2, bu2, sstep, state);
    }

    final_kernel<<<(NROWS + 255) / 256, 256>>>((float*)d_out);
}

// round 14
// speedup vs baseline: 1.5716x; 1.5716x over previous
#include <cuda_runtime.h>
#include <math.h>
#include <stdint.h>

// ---------------- problem constants ----------------
#define BB      64
#define NP      377
#define NROWS   (BB * NP)        // 24128 = 377 * 64
#define CIN     384
#define HID     128
#define H2X     256
#define SD      16
#define KNEI    6
#define PIN_DIM (SD * (KNEI + 1)) // 112
#define NSTEPS  16
#define FH      37
#define DHH     518
#define CCHUNK  8                // channels per sample_feat block

// fused_step dynamic smem layout (floats)
#define FS_AS_OFF   0                       // As[2][16][68]  = 2176
#define FS_WS_OFF   2176                    // Ws[2][16][128] = 4096
#define FS_HS_OFF   (2176 + 4096)           // Hs[128][68]    = 8704 (also reduce buf)
#define FS_B1_OFF   (FS_HS_OFF + 8704)      // bp2s[128]
#define FS_B2_OFF   (FS_B1_OFF + 128)       // bu1s[128]
#define FS_B3_OFF   (FS_B2_OFF + 128)       // bu2s[16]
#define FS_TOTAL_F  (FS_B3_OFF + 16)        // 15248 floats
#define FS_TOTAL_B  (FS_TOTAL_F * 4)        // 60992 bytes

typedef unsigned long long u64;

// ---- packed f32x2 helpers (sm_100a) -----------------------------------------
__device__ __forceinline__ u64 bcast2(float x) {
    u64 r;
    asm("mov.b64 %0, {%1, %1};" : "=l"(r) : "f"(x));
    return r;
}
__device__ __forceinline__ void fma2(u64& acc, u64 a, u64 w) {
    asm("fma.rn.f32x2 %0, %1, %2, %0;" : "+l"(acc) : "l"(a), "l"(w));
}
__device__ __forceinline__ void unpack2(u64 v, float& lo, float& hi) {
    asm("mov.b64 {%0, %1}, %2;" : "=f"(lo), "=f"(hi) : "l"(v));
}

// ---- cp.async helpers --------------------------------------------------------
__device__ __forceinline__ void cp16(void* dst_smem, const void* src_gmem) {
    uint32_t d = (uint32_t)__cvta_generic_to_shared(dst_smem);
    asm volatile("cp.async.cg.shared.global [%0], [%1], 16;" :: "r"(d), "l"(src_gmem));
}
__device__ __forceinline__ void cp_commit() {
    asm volatile("cp.async.commit_group;");
}
__device__ __forceinline__ void cp_wait0() {
    asm volatile("cp.async.wait_group 0;" ::: "memory");
}

// ---------------- scratch ----------------------------------------------------
__device__ float g_Fs[(size_t)NROWS * CIN];
__device__ float g_dep[NROWS];
__device__ float g_bufA[(size_t)NROWS * H2X];
__device__ float g_bufB[(size_t)NROWS * HID];
__device__ float g_init[(size_t)NROWS * SD];
__device__ float g_state[(size_t)NROWS * SD];
__device__ float g_pin[(size_t)NROWS * PIN_DIM];

// ---------------- feature bilinear sampling (smem-image, coalesced) ----------
__global__ void __launch_bounds__(256) sample_feat_kernel(
        const float* __restrict__ feat,
        const float* __restrict__ sx,
        const float* __restrict__ sy) {
    __shared__ float img[CCHUNK * FH * FH];   // 8 * 1369 floats = 43808 B

    int b  = blockIdx.x;
    int c0 = blockIdx.y * CCHUNK;

    const float* src = feat + ((size_t)b * CIN + c0) * FH * FH;
    for (int i = threadIdx.x; i < CCHUNK * FH * FH; i += 256) img[i] = src[i];
    __syncthreads();

    for (int it = threadIdx.x; it < NP * CCHUNK; it += 256) {
        int n = it >> 3, cc = it & 7;
        float gx = sx[n], gy = sy[n];
        float ix = fminf(fmaxf((gx + 1.0f) * 0.5f * (float)(FH - 1), 0.0f), (float)(FH - 1));
        float iy = fminf(fmaxf((gy + 1.0f) * 0.5f * (float)(FH - 1), 0.0f), (float)(FH - 1));
        int x0 = (int)floorf(ix), y0 = (int)floorf(iy);
        int x1 = min(x0 + 1, FH - 1), y1 = min(y0 + 1, FH - 1);
        float wx = ix - (float)x0, wy = iy - (float)y0;
        float w00 = (1.0f - wx) * (1.0f - wy);
        float w01 = wx * (1.0f - wy);
        float w10 = (1.0f - wx) * wy;
        float w11 = wx * wy;

        const float* p = img + cc * FH * FH;
        float v = p[y0 * FH + x0] * w00 + p[y0 * FH + x1] * w01 +
                  p[y1 * FH + x0] * w10 + p[y1 * FH + x1] * w11;
        g_Fs[((size_t)b * NP + n) * CIN + c0 + cc] = v;
    }
}

// ---------------- depth bilinear sampling ------------------------------------
__global__ void sample_depth_kernel(const float* __restrict__ depth,
                                    const float* __restrict__ sx,
                                    const float* __restrict__ sy) {
    int row = blockIdx.x * blockDim.x + threadIdx.x;
    if (row >= NROWS) return;
    int b = row / NP, n = row % NP;
    float gx = sx[n], gy = sy[n];
    float jx = fminf(fmaxf((gx + 1.0f) * 0.5f * (float)(DHH - 1), 0.0f), (float)(DHH - 1));
    float jy = fminf(fmaxf((gy + 1.0f) * 0.5f * (float)(DHH - 1), 0.0f), (float)(DHH - 1));
    int a0 = (int)floorf(jx), c0 = (int)floorf(jy);
    int a1 = min(a0 + 1, DHH - 1), c1 = min(c0 + 1, DHH - 1);
    float ux = jx - (float)a0, uy = jy - (float)c0;
    const float* dp = depth + (size_t)b * DHH * DHH;
    float v = dp[c0 * DHH + a0] * (1.0f - ux) * (1.0f - uy) +
              dp[c0 * DHH + a1] * ux * (1.0f - uy) +
              dp[c1 * DHH + a0] * (1.0f - ux) * uy +
              dp[c1 * DHH + a1] * ux * uy;
    g_dep[row] = v;
}

// ---- 8-deep k micro-kernel, 8x8 tile, packed --------------------------------
__device__ __forceinline__ void mma_tile8(
    u64 acc64[8][4], const float (*As8)[68], const float (*Ws8)[128],
    int r8, int c16) {
#pragma unroll
    for (int kk = 0; kk < 8; kk++) {
        float4 a0 = *reinterpret_cast<const float4*>(&As8[kk][r8 * 4]);
        float4 a1 = *reinterpret_cast<const float4*>(&As8[kk][32 + r8 * 4]);
        ulonglong2 wva = *reinterpret_cast<const ulonglong2*>(&Ws8[kk][c16 * 8]);
        ulonglong2 wvb = *reinterpret_cast<const ulonglong2*>(&Ws8[kk][c16 * 8 + 4]);
        u64 wpk[4] = {wva.x, wva.y, wvb.x, wvb.y};
        u64 ab[8] = {bcast2(a0.x), bcast2(a0.y), bcast2(a0.z), bcast2(a0.w),
                     bcast2(a1.x), bcast2(a1.y), bcast2(a1.z), bcast2(a1.w)};
#pragma unroll
        for (int i = 0; i < 8; i++)
#pragma unroll
            for (int j = 0; j < 4; j++) fma2(acc64[i][j], ab[i], wpk[j]);
    }
}

// ---- two-round reduction (4096-float buffer), rows [r*4, r*4+4) -------------
__device__ __forceinline__ void red_store(float* red, u64 acc64[8][4], int r, int wt) {
#pragma unroll
    for (int i = 0; i < 4; i++)
#pragma unroll
        for (int j = 0; j < 4; j++) {
            float lo, hi;
            unpack2(acc64[r * 4 + i][j], lo, hi);
            red[(i * 8 + 2 * j) * 128 + wt] = lo;
            red[(i * 8 + 2 * j + 1) * 128 + wt] = hi;
        }
}
__device__ __forceinline__ void red_add(const float* red, float accf[8][8], int r, int wt) {
#pragma unroll
    for (int i = 0; i < 4; i++)
#pragma unroll
        for (int j2 = 0; j2 < 8; j2++)
            accf[r * 4 + i][j2] += red[(i * 8 + j2) * 128 + wt];
}

// ---- single-round reduction (8192-float buffer), all 8 rows -----------------
__device__ __forceinline__ void red_store_all(float* red, u64 acc64[8][4], int wt) {
#pragma unroll
    for (int i = 0; i < 8; i++)
#pragma unroll
        for (int j = 0; j < 4; j++) {
            float lo, hi;
            unpack2(acc64[i][j], lo, hi);
            red[(i * 8 + 2 * j) * 128 + wt] = lo;
            red[(i * 8 + 2 * j + 1) * 128 + wt] = hi;
        }
}
__device__ __forceinline__ void red_add_all(const float* red, float accf[8][8], int wt) {
#pragma unroll
    for (int i = 0; i < 8; i++)
#pragma unroll
        for (int j2 = 0; j2 < 8; j2++)
            accf[i][j2] += red[(i * 8 + j2) * 128 + wt];
}

// ---------------- 64x128 GEMM, 256 thr, K-split groups, cp.async W staging ---
template <int EPI>
__global__ void __launch_bounds__(256, 2)
gemm64x128(const float* __restrict__ A, const float* __restrict__ W,
           const float* __restrict__ bias, float* __restrict__ C,
           int K, int N) {
    __shared__ __align__(16) float As[2][16][68];
    __shared__ __align__(16) float Ws[2][16][128];

    int m0 = blockIdx.x * 64;
    int n0 = blockIdx.y * 128;
    int tid = threadIdx.x;
    int g   = tid >> 7;
    int wt  = tid & 127;
    int r8 = wt & 7, c16 = wt >> 3;

    int am = tid >> 2;
    int aq = (tid & 3) * 4;
    int wk = tid >> 5;             // 0..7
    int wn = (tid & 31) * 4;

    u64 acc64[8][4];
#pragma unroll
    for (int i = 0; i < 8; i++)
#pragma unroll
        for (int j = 0; j < 4; j++) acc64[i][j] = 0ull;

    // preload tile 0: A via regs, W via cp.async
    {
        float4 v = *reinterpret_cast<const float4*>(&A[(size_t)(m0 + am) * K + aq]);
        As[0][aq + 0][am] = v.x;
        As[0][aq + 1][am] = v.y;
        As[0][aq + 2][am] = v.z;
        As[0][aq + 3][am] = v.w;
#pragma unroll
        for (int i = 0; i < 2; i++) {
            int k = wk + i * 8;
            cp16(&Ws[0][k][wn], &W[(size_t)k * N + n0 + wn]);
        }
        cp_commit();
    }
    cp_wait0();
    __syncthreads();

    int KT = K >> 4;
    int p = 0;
    for (int t = 0; t < KT; t++) {
        float4 pa;
        bool has = (t + 1 < KT);
        int q = p ^ 1;
        if (has) {
            int k0 = (t + 1) << 4;
#pragma unroll
            for (int i = 0; i < 2; i++) {
                int k = wk + i * 8;
                cp16(&Ws[q][k][wn], &W[(size_t)(k0 + k) * N + n0 + wn]);
            }
            cp_commit();
            pa = *reinterpret_cast<const float4*>(&A[(size_t)(m0 + am) * K + k0 + aq]);
        }

        mma_tile8(acc64,
                  reinterpret_cast<const float (*)[68]>(&As[p][g * 8][0]),
                  reinterpret_cast<const float (*)[128]>(&Ws[p][g * 8][0]),
                  r8, c16);

        if (has) {
            As[q][aq + 0][am] = pa.x;
            As[q][aq + 1][am] = pa.y;
            As[q][aq + 2][am] = pa.z;
            As[q][aq + 3][am] = pa.w;
            cp_wait0();
        }
        __syncthreads();
        p ^= 1;
    }

    // ---- two-round cross-group reduction (red buffer aliases Ws) ----
    float* red = &Ws[0][0][0];
    float accf[8][8];
    if (g == 0) {
#pragma unroll
        for (int i = 0; i < 8; i++)
#pragma unroll
            for (int j = 0; j < 4; j++) unpack2(acc64[i][j], accf[i][2 * j], accf[i][2 * j + 1]);
    }
#pragma unroll
    for (int r = 0; r < 2; r++) {
        if (g == 1) red_store(red, acc64, r, wt);
        __syncthreads();
        if (g == 0) red_add(red, accf, r, wt);
        __syncthreads();
    }

    if (g == 0) {
        float bb[8];
#pragma unroll
        for (int j = 0; j < 8; j++) bb[j] = bias[n0 + c16 * 8 + j];
#pragma unroll
        for (int h = 0; h < 2; h++) {
#pragma unroll
            for (int i = 0; i < 4; i++) {
                int m = m0 + h * 32 + r8 * 4 + i;
                int ai = h * 4 + i;
                float v[8];
#pragma unroll
                for (int j = 0; j < 8; j++) {
                    v[j] = accf[ai][j] + bb[j];
                    if (EPI == 0) v[j] = fmaxf(v[j], 0.0f);
                }
                float4* cp = reinterpret_cast<float4*>(&C[(size_t)m * N + n0 + c16 * 8]);
                cp[0] = make_float4(v[0], v[1], v[2], v[3]);
                cp[1] = make_float4(v[4], v[5], v[6], v[7]);
            }
        }
    }
}

// ---------------- small GEMM (N=16), used once for wi3 -----------------------
template <int BM, int BN, int BK, int TM, int TN, int EPI>
__global__ void gemm_kernel(const float* __restrict__ A,
                            const float* __restrict__ W,
                            const float* __restrict__ bias,
                            float* __restrict__ C,
                            int K, int N) {
    constexpr int TX = BN / TN;
    constexpr int TY = BM / TM;
    static_assert(TX * TY == 256, "256 threads");
    constexpr int AS = BM + 4;
    __shared__ float As[BK][AS];
    __shared__ float Ws[BK][BN];

    int m0 = blockIdx.x * BM;
    int n0 = blockIdx.y * BN;
    int tid = threadIdx.x;
    int tx = tid % TX, ty = tid / TX;

    float acc[TM][TN];
#pragma unroll
    for (int i = 0; i < TM; i++)
#pragma unroll
        for (int j = 0; j < TN; j++) acc[i][j] = 0.0f;

    int am = tid >> 2;
    int aq = (tid & 3) * 4;

    for (int k0 = 0; k0 < K; k0 += BK) {
        {
            const float4 v = *reinterpret_cast<const float4*>(
                &A[(size_t)(m0 + am) * K + k0 + aq]);
            As[aq + 0][am] = v.x;
            As[aq + 1][am] = v.y;
            As[aq + 2][am] = v.z;
            As[aq + 3][am] = v.w;
        }
        for (int i = tid; i < BK * BN; i += 256) {
            int k = i / BN, n = i % BN;
            Ws[k][n] = W[(size_t)(k0 + k) * N + n0 + n];
        }
        __syncthreads();
#pragma unroll
        for (int kk = 0; kk < BK; kk++) {
            float a[TM], w[TN];
#pragma unroll
            for (int i = 0; i < TM; i++) a[i] = As[kk][ty * TM + i];
#pragma unroll
            for (int j = 0; j < TN; j++) w[j] = Ws[kk][tx * TN + j];
#pragma unroll
            for (int i = 0; i < TM; i++)
#pragma unroll
                for (int j = 0; j < TN; j++) acc[i][j] += a[i] * w[j];
        }
        __syncthreads();
    }
#pragma unroll
    for (int i = 0; i < TM; i++) {
        int m = m0 + ty * TM + i;
#pragma unroll
        for (int j = 0; j < TN; j++) {
            int n = n0 + tx * TN + j;
            float v = acc[i][j] + bias[n];
            if (EPI == 0) v = fmaxf(v, 0.0f);
            C[(size_t)m * N + n] = v;
        }
    }
}

// ---------------- fused wp2 -> wu1 -> wu2 -> state update --------------------
__global__ void __launch_bounds__(256, 2)
fused_step(const float* __restrict__ A,           // g_bufA (h1), row len 256
           const float* __restrict__ wp2, const float* __restrict__ bp2,
           const float* __restrict__ wu1, const float* __restrict__ bu1,
           const float* __restrict__ wu2, const float* __restrict__ bu2,
           const float* __restrict__ sstep,
           float* __restrict__ state) {
    extern __shared__ __align__(16) float dyn[];
    float (*As)[16][68]  = reinterpret_cast<float (*)[16][68]>(dyn + FS_AS_OFF);
    float (*Ws)[16][128] = reinterpret_cast<float (*)[16][128]>(dyn + FS_WS_OFF);
    float (*Hs)[68]      = reinterpret_cast<float (*)[68]>(dyn + FS_HS_OFF);
    float* redH = dyn + FS_HS_OFF;   // 8704-float Hs area; 8192 used (1-round red)
    float* bp2s = dyn + FS_B1_OFF;
    float* bu1s = dyn + FS_B2_OFF;
    float* bu2s = dyn + FS_B3_OFF;

    int m0 = blockIdx.x * 64;
    int tid = threadIdx.x;
    int g   = tid >> 7;
    int wt  = tid & 127;
    int r8 = wt & 7, c16 = wt >> 3;
    int am = tid >> 2;
    int aq = (tid & 3) * 4;
    int wk = tid >> 5;
    int wn = (tid & 31) * 4;

    if (tid < 128) { bp2s[tid] = bp2[tid]; bu1s[tid] = bu1[tid]; }
    if (tid < 16)  { bu2s[tid] = bu2[tid]; }

    u64 acc64[8][4];
#pragma unroll
    for (int i = 0; i < 8; i++)
#pragma unroll
        for (int j = 0; j < 4; j++) acc64[i][j] = 0ull;

    // ---- phase 1: h2 = relu(h1 @ wp2 + bp2), K=256 ----
    {
        float4 v = *reinterpret_cast<const float4*>(&A[(size_t)(m0 + am) * 256 + aq]);
        As[0][aq + 0][am] = v.x;
        As[0][aq + 1][am] = v.y;
        As[0][aq + 2][am] = v.z;
        As[0][aq + 3][am] = v.w;
#pragma unroll
        for (int i = 0; i < 2; i++) {
            int k = wk + i * 8;
            cp16(&Ws[0][k][wn], &wp2[(size_t)k * 128 + wn]);
        }
        cp_commit();
    }
    cp_wait0();
    __syncthreads();

    int p = 0;
    for (int t = 0; t < 16; t++) {
        float4 pa;
        bool has = (t + 1 < 16);
        int q = p ^ 1;
        if (has) {
            int k0 = (t + 1) << 4;
#pragma unroll
            for (int i = 0; i < 2; i++) {
                int k = wk + i * 8;
                cp16(&Ws[q][k][wn], &wp2[(size_t)(k0 + k) * 128 + wn]);
            }
            cp_commit();
            pa = *reinterpret_cast<const float4*>(&A[(size_t)(m0 + am) * 256 + k0 + aq]);
        }
        mma_tile8(acc64,
                  reinterpret_cast<const float (*)[68]>(&As[p][g * 8][0]),
                  reinterpret_cast<const float (*)[128]>(&Ws[p][g * 8][0]),
                  r8, c16);
        if (has) {
            As[q][aq + 0][am] = pa.x;
            As[q][aq + 1][am] = pa.y;
            As[q][aq + 2][am] = pa.z;
            As[q][aq + 3][am] = pa.w;
            cp_wait0();
        }
        __syncthreads();
        p ^= 1;
    }

    // single-round reduction + h2 store + wu1 tile-0 async stage
    {
        float accf[8][8];
        if (g == 1) red_store_all(redH, acc64, wt);
        if (g == 0) {
#pragma unroll
            for (int i = 0; i < 8; i++)
#pragma unroll
                for (int j = 0; j < 4; j++) unpack2(acc64[i][j], accf[i][2 * j], accf[i][2 * j + 1]);
        }
        __syncthreads();
        if (g == 0) red_add_all(redH, accf, wt);
        __syncthreads();   // all reads of redH done before Hs overwrite
        if (g == 0) {
#pragma unroll
            for (int j = 0; j < 8; j++) {
                int n = c16 * 8 + j;
                float v0[4], v1[4];
#pragma unroll
                for (int i = 0; i < 4; i++) v0[i] = fmaxf(accf[i][j] + bp2s[n], 0.0f);
#pragma unroll
                for (int i = 0; i < 4; i++) v1[i] = fmaxf(accf[4 + i][j] + bp2s[n], 0.0f);
                *reinterpret_cast<float4*>(&Hs[n][r8 * 4])      = make_float4(v0[0], v0[1], v0[2], v0[3]);
                *reinterpret_cast<float4*>(&Hs[n][32 + r8 * 4]) = make_float4(v1[0], v1[1], v1[2], v1[3]);
            }
        }
#pragma unroll
        for (int i = 0; i < 2; i++) {
            int k = wk + i * 8;
            cp16(&Ws[0][k][wn], &wu1[(size_t)k * 128 + wn]);
        }
        cp_commit();
        cp_wait0();
        __syncthreads();
    }

    // ---- phase 2: dh = relu(h2 @ wu1 + bu1), K=128, A in Hs ----
#pragma unroll
    for (int i = 0; i < 8; i++)
#pragma unroll
        for (int j = 0; j < 4; j++) acc64[i][j] = 0ull;

    p = 0;
    for (int c = 0; c < 8; c++) {
        bool has = (c + 1 < 8);
        int q = p ^ 1;
        if (has) {
            int k0 = (c + 1) << 4;
#pragma unroll
            for (int i = 0; i < 2; i++) {
                int k = wk + i * 8;
                cp16(&Ws[q][k][wn], &wu1[(size_t)(k0 + k) * 128 + wn]);
            }
            cp_commit();
        }
        mma_tile8(acc64,
                  reinterpret_cast<const float (*)[68]>(&Hs[c * 16 + g * 8][0]),
                  reinterpret_cast<const float (*)[128]>(&Ws[p][g * 8][0]),
                  r8, c16);
        if (has) cp_wait0();
        __syncthreads();
        p ^= 1;
    }

    // single-round reduction + dh store + wu2 staging
    {
        float accf[8][8];
        if (g == 1) red_store_all(redH, acc64, wt);
        if (g == 0) {
#pragma unroll
            for (int i = 0; i < 8; i++)
#pragma unroll
                for (int j = 0; j < 4; j++) unpack2(acc64[i][j], accf[i][2 * j], accf[i][2 * j + 1]);
        }
        __syncthreads();
        if (g == 0) red_add_all(redH, accf, wt);
        __syncthreads();   // redH reads done before Hs overwrite
        if (g == 0) {
#pragma unroll
            for (int j = 0; j < 8; j++) {
                int n = c16 * 8 + j;
                float v0[4], v1[4];
#pragma unroll
                for (int i = 0; i < 4; i++) v0[i] = fmaxf(accf[i][j] + bu1s[n], 0.0f);
#pragma unroll
                for (int i = 0; i < 4; i++) v1[i] = fmaxf(accf[4 + i][j] + bu1s[n], 0.0f);
                *reinterpret_cast<float4*>(&Hs[n][r8 * 4])      = make_float4(v0[0], v0[1], v0[2], v0[3]);
                *reinterpret_cast<float4*>(&Hs[n][32 + r8 * 4]) = make_float4(v1[0], v1[1], v1[2], v1[3]);
            }
        }
        {
            float* wflat = &Ws[0][0][0];
#pragma unroll
            for (int i = 0; i < 2; i++) {
                int f = (tid + i * 256) * 4;   // 2048 floats
                cp16(&wflat[f], &wu2[f]);
            }
            cp_commit();
            cp_wait0();
        }
        __syncthreads();
    }

    // ---- phase 3: delta = dh @ wu2 + bu2; state += step*delta ----
    {
        const float* wflat = &Ws[0][0][0];
        int col = tid & 15;
        int rg  = tid >> 4;   // 0..15 -> rows rg*4..+3
        float acc3[4];
#pragma unroll
        for (int i = 0; i < 4; i++) acc3[i] = 0.0f;
#pragma unroll 8
        for (int kk = 0; kk < 128; kk++) {
            float w = wflat[kk * 16 + col];
            float4 a4 = *reinterpret_cast<const float4*>(&Hs[kk][rg * 4]);
            acc3[0] += a4.x * w; acc3[1] += a4.y * w;
            acc3[2] += a4.z * w; acc3[3] += a4.w * w;
        }
        float stp = sstep[0];
        float bv = bu2s[col];
#pragma unroll
        for (int i = 0; i < 4; i++) {
            int m = m0 + rg * 4 + i;
            state[(size_t)m * SD + col] += stp * (acc3[i] + bv);
        }
    }
}

// ---------------- initial state build ----------------------------------------
__global__ void init_state_kernel(const float* __restrict__ sx,
                                  const float* __restrict__ sy,
                                  const float* __restrict__ doff) {
    int row = blockIdx.x * blockDim.x + threadIdx.x;
    if (row >= NROWS) return;
    int n = row % NP;
    const float* ini = g_init + (size_t)row * SD;
    float* st = g_state + (size_t)row * SD;
    st[0] = sx[n] + ini[0] * 0.15f;
    st[1] = sy[n] + ini[1] * 0.15f;
    st[2] = doff[0] + g_dep[row] * -2.0f;
#pragma unroll
    for (int i = 3; i < SD; i++) st[i] = ini[i];
}

// ---------------- fused kNN + pin gather (2 blocks per batch) ----------------
__global__ void __launch_bounds__(384) neighpin_kernel() {
    __shared__ float st[NP * SD];   // 24128 B
    int b = blockIdx.x >> 1;
    int half = blockIdx.x & 1;
    int t = threadIdx.x;

    const float4* gs = reinterpret_cast<const float4*>(g_state + (size_t)b * NP * SD);
    float4* s4 = reinterpret_cast<float4*>(st);
    for (int i = t; i < NP * SD / 4; i += 384) s4[i] = gs[i];
    __syncthreads();

    int pt = half * 189 + t;
    if (t >= 189 || pt >= NP) return;

    float bd[KNEI + 1];
    int bi[KNEI + 1];
#pragma unroll
    for (int i = 0; i <= KNEI; i++) { bd[i] = 3.4e38f; bi[i] = -1; }

    float x = st[pt * SD + 0], y = st[pt * SD + 1], z = st[pt * SD + 2];
    for (int j = 0; j < NP; j++) {
        float dx = x - st[j * SD + 0];
        float dy = y - st[j * SD + 1];
        float dz = z - st[j * SD + 2];
        float d2 = dx * dx + dy * dy + dz * dz;
        if (d2 < bd[KNEI]) {
            int p = KNEI;
            while (p > 0 && bd[p - 1] > d2) {
                bd[p] = bd[p - 1];
                bi[p] = bi[p - 1];
                p--;
            }
            bd[p] = d2;
            bi[p] = j;
        }
    }

    float4* p4 = reinterpret_cast<float4*>(g_pin + (size_t)(b * NP + pt) * PIN_DIM);
    const float4* self = reinterpret_cast<const float4*>(&st[pt * SD]);
#pragma unroll
    for (int q = 0; q < 4; q++) p4[q] = self[q];
#pragma unroll
    for (int k = 0; k < KNEI; k++) {
        const float4* nb = reinterpret_cast<const float4*>(&st[bi[k + 1] * SD]);
#pragma unroll
        for (int q = 0; q < 4; q++) p4[4 + k * 4 + q] = nb[q];
    }
}

// ---------------- postprocess ------------------------------------------------
__device__ __forceinline__ float sgnf(float x) {
    return (x > 0.0f) ? 1.0f : ((x < 0.0f) ? -1.0f : 0.0f);
}

__global__ void final_kernel(float* __restrict__ out) {
    int row = blockIdx.x * blockDim.x + threadIdx.x;
    if (row >= NROWS) return;
    const float* s = g_state + (size_t)row * SD;
    float o[14];
    o[0] = s[0]; o[1] = s[1]; o[2] = s[2];

#pragma unroll
    for (int i = 0; i < 3; i++) {
        float tv = fminf(fmaxf(s[3 + i], -10.0f), 20.0f) + 1.0f;
        float sp = log1pf(expf(tv));
        o[3 + i] = fminf(fmaxf(sp * 0.15f, 1e-6f), 2.0f);
    }

    const float eps = 1e-8f;
    float a1x = s[6], a1y = s[7], a1z = s[8];
    float a2x = s[9], a2y = s[10], a2z = s[11];
    float n1 = sqrtf(a1x * a1x + a1y * a1y + a1z * a1z) + eps;
    float b1x = a1x / n1, b1y = a1y / n1, b1z = a1z / n1;
    float dd = b1x * a2x + b1y * a2y + b1z * a2z;
    float pxv = a2x - dd * b1x, pyv = a2y - dd * b1y, pzv = a2z - dd * b1z;
    float n2 = sqrtf(pxv * pxv + pyv * pyv + pzv * pzv) + eps;
    float b2x = pxv / n2, b2y = pyv / n2, b2z = pzv / n2;
    float b3x = b1y * b2z - b1z * b2y;
    float b3y = b1z * b2x - b1x * b2z;
    float b3z = b1x * b2y - b1y * b2x;
    float m00 = b1x, m11 = b2y, m22 = b3z;
    float qw = 0.5f * sqrtf(fmaxf(1.0f + m00 + m11 + m22, 0.0f) + eps);
    float qx = 0.5f * sqrtf(fmaxf(1.0f + m00 - m11 - m22, 0.0f) + eps) * sgnf(b2z - b3y);
    float qy = 0.5f * sqrtf(fmaxf(1.0f - m00 + m11 - m22, 0.0f) + eps) * sgnf(b3x - b1z);
    float qz = 0.5f * sqrtf(fmaxf(1.0f - m00 - m11 + m22, 0.0f) + eps) * sgnf(b1y - b2x);
    float qn = sqrtf(qw * qw + qx * qx + qy * qy + qz * qz) + eps;
    o[6] = qw / qn; o[7] = qx / qn; o[8] = qy / qn; o[9] = qz / qn;

    o[10] = 1.0f / (1.0f + expf(-s[12]));
    o[11] = 1.0f / (1.0f + expf(-s[13]));
    o[12] = 1.0f / (1.0f + expf(-s[14]));
    o[13] = 1.0f / (1.0f + expf(-s[15]));

    float* op = out + (size_t)row * 14;
#pragma unroll
    for (int i = 0; i < 14; i++) op[i] = o[i];
}

// ---------------- launch ------------------------------------------------------
extern "C" void kernel_launch(void* const* d_in, const int* in_sizes, int n_in,
                              void* d_out, int out_size) {
    const float* feat  = (const float*)d_in[0];
    const float* depth = (const float*)d_in[1];
    const float* sx    = (const float*)d_in[2];
    const float* sy    = (const float*)d_in[3];
    const float* doff  = (const float*)d_in[4];
    const float* sstep = (const float*)d_in[5];
    const float* wi1 = (const float*)d_in[6];
    const float* bi1 = (const float*)d_in[7];
    const float* wi2 = (const float*)d_in[8];
    const float* bi2 = (const float*)d_in[9];
    const float* wi3 = (const float*)d_in[10];
    const float* bi3 = (const float*)d_in[11];
    const float* wp1 = (const float*)d_in[12];
    const float* bp1 = (const float*)d_in[13];
    const float* wp2 = (const float*)d_in[14];
    const float* bp2 = (const float*)d_in[15];
    const float* wu1 = (const float*)d_in[16];
    const float* bu1 = (const float*)d_in[17];
    const float* wu2 = (const float*)d_in[18];
    const float* bu2 = (const float*)d_in[19];

    cudaFuncSetAttribute(fused_step, cudaFuncAttributeMaxDynamicSharedMemorySize,
                         FS_TOTAL_B);

    void *pFs, *pA, *pB, *pInit, *pState, *pPin;
    cudaGetSymbolAddress(&pFs, g_Fs);
    cudaGetSymbolAddress(&pA, g_bufA);
    cudaGetSymbolAddress(&pB, g_bufB);
    cudaGetSymbolAddress(&pInit, g_init);
    cudaGetSymbolAddress(&pState, g_state);
    cudaGetSymbolAddress(&pPin, g_pin);
    float* Fs = (float*)pFs;
    float* bufA = (float*)pA;
    float* bufB = (float*)pB;
    float* initb = (float*)pInit;
    float* state = (float*)pState;
    float* pin = (float*)pPin;

    const int MB = NROWS / 64;  // 377

    // launches 0,1: sampling (launch #3 = gemm64x128 wi2 for ncu)
    sample_feat_kernel<<<dim3(BB, CIN / CCHUNK), 256>>>(feat, sx, sy);
    sample_depth_kernel<<<(NROWS + 127) / 128, 128>>>(depth, sx, sy);

    // launch 2: wi1 (K=384, N=256); launch 3: wi2 (K=256, N=128) <- profiled
    gemm64x128<0><<<dim3(MB, 2), 256>>>(Fs, wi1, bi1, bufA, CIN, H2X);
    gemm64x128<0><<<dim3(MB, 1), 256>>>(bufA, wi2, bi2, bufB, H2X, HID);
    gemm_kernel<64, 16, 16, 4, 1, 1><<<dim3(MB, 1), 256>>>(bufB, wi3, bi3, initb, HID, SD);

    init_state_kernel<<<(NROWS + 255) / 256, 256>>>(sx, sy, doff);

    for (int s = 0; s < NSTEPS; s++) {
        neighpin_kernel<<<BB * 2, 384>>>();
        gemm64x128<0><<<dim3(MB, 2), 256>>>(pin, wp1, bp1, bufA, PIN_DIM, H2X);
        fused_step<<<MB, 256, FS_TOTAL_B>>>(bufA, wp2, bp2, wu1, bu1, wu2, bu2, sstep, state);
    }

    final_kernel<<<(NROWS + 255) / 256, 256>>>((float*)d_out);
}